// round 12
// baseline (speedup 1.0000x reference)
#include <cuda_runtime.h>

#define PSSM_BATCH  2
#define PSSM_SEQ    2048
#define PSSM_DIN    128
#define PSSM_NST    64
#define PSSM_NC     32      // chunks per sequence
#define PSSM_CL     64      // chunk length
#define PSSM_LOG2E  1.4426950408889634f

// ---- scratch (static device arrays; no allocation) ----
__device__ float g_xc   [PSSM_BATCH*PSSM_DIN*PSSM_SEQ];            // (b,d,l)
__device__ float g_delta[PSSM_BATCH*PSSM_DIN*PSSM_SEQ];            // (b,d,l) sigmoid applied
__device__ float g_u    [PSSM_BATCH*PSSM_DIN*PSSM_SEQ];            // (b,d,l) delta*x_conv
__device__ float g_v    [PSSM_BATCH*PSSM_DIN*PSSM_SEQ];            // (b,d,l) x_conv
__device__ float g_B    [PSSM_BATCH*PSSM_SEQ*PSSM_NST];            // (b,l,n)
__device__ float g_C    [PSSM_BATCH*PSSM_SEQ*PSSM_NST];            // (b,l,n)
__device__ float g_a2   [PSSM_NST];                                // rowsum(A)*log2(e)
__device__ float g_hloc [PSSM_BATCH*2*PSSM_NC*PSSM_DIN*PSSM_NST];  // (b,dir,c,d,n)
__device__ float g_carry[PSSM_BATCH*2*PSSM_NC*PSSM_DIN*PSSM_NST];  // (b,dir,c,d,n)
__device__ float g_dS   [PSSM_BATCH*PSSM_NC*PSSM_DIN];             // (b,c,d)

// scanC dynamic smem layout (floats)
#define SMC_B     0                       // 64*64 = 4096
#define SMC_C     4096                    // 4096
#define SMC_TILE  8192                    // 8 warps x (16 x 36) = 4608
#define SMC_YSUM  12800                   // 64 x 33 = 2112
#define SMC_VS    14912                   // 16 x 65 = 1040
#define SMC_TOTAL_BYTES (15952 * 4)       // 63808 B

// ============================================================
// Stage 1: projection xp = x @ W^T.
// grid (64, 12), block 256.  bx -> 64-token tile, by -> 32 outputs.
// ============================================================
__global__ void __launch_bounds__(256) pssm_proj_kernel(
    const float* __restrict__ x,
    const float* __restrict__ W,
    const float* __restrict__ A)
{
    __shared__ float xsT[64 * 65];    // [k][t], pad 65  (16.6KB)
    __shared__ float Wsm[32 * 64];    // [i][k]          (8KB)

    const int tid = threadIdx.x;
    const int og  = blockIdx.y;                  // 0..11
    const int t0  = blockIdx.x * 64;             // global token base

    if (blockIdx.x == 0 && blockIdx.y == 0 && tid < PSSM_NST) {
        float s = 0.f;
        const float* ar = A + tid * PSSM_NST;
        #pragma unroll 8
        for (int j = 0; j < PSSM_NST; j++) s += ar[j];
        g_a2[tid] = s * PSSM_LOG2E;
    }

    {
        const float4* wsrc = (const float4*)(W + og * 32 * 64);
        float4* wdst = (float4*)Wsm;
        wdst[tid]       = __ldg(&wsrc[tid]);
        wdst[tid + 256] = __ldg(&wsrc[tid + 256]);
    }

    #pragma unroll
    for (int i = 0; i < 4; i++) {
        const int f  = tid + 256 * i;
        const int t  = f >> 4;
        const int c4 = (f & 15) * 4;
        const float4 v = __ldg((const float4*)(x + (t0 + t) * 64 + c4));
        xsT[(c4 + 0) * 65 + t] = v.x;
        xsT[(c4 + 1) * 65 + t] = v.y;
        xsT[(c4 + 2) * 65 + t] = v.z;
        xsT[(c4 + 3) * 65 + t] = v.w;
    }
    __syncthreads();

    const int oc = tid >> 6;          // 0..3
    const int t  = tid & 63;
    const int token = t0 + t;
    const int b = token >> 11;
    const int l = token & 2047;

    float acc[8] = {0.f, 0.f, 0.f, 0.f, 0.f, 0.f, 0.f, 0.f};

    #pragma unroll 4
    for (int k4 = 0; k4 < 16; k4++) {
        const int k = k4 * 4;
        const float x0 = xsT[(k + 0) * 65 + t];
        const float x1 = xsT[(k + 1) * 65 + t];
        const float x2 = xsT[(k + 2) * 65 + t];
        const float x3 = xsT[(k + 3) * 65 + t];
        #pragma unroll
        for (int i = 0; i < 8; i++) {
            const float4 w4 = *(const float4*)&Wsm[(oc * 8 + i) * 64 + k];
            acc[i] = fmaf(w4.x, x0, acc[i]);
            acc[i] = fmaf(w4.y, x1, acc[i]);
            acc[i] = fmaf(w4.z, x2, acc[i]);
            acc[i] = fmaf(w4.w, x3, acc[i]);
        }
    }

    const int obase = og * 32 + oc * 8;          // block-uniform segment
    if (obase < 128) {
        #pragma unroll
        for (int i = 0; i < 8; i++)
            g_xc[(b * PSSM_DIN + obase + i) * PSSM_SEQ + l] = acc[i];
    } else if (obase < 256) {
        #pragma unroll
        for (int i = 0; i < 8; i++)
            g_delta[(b * PSSM_DIN + (obase - 128 + i)) * PSSM_SEQ + l] =
                __fdividef(1.f, 1.f + __expf(-acc[i]));
    } else if (obase < 320) {
        float4* dst = (float4*)&g_B[(b * PSSM_SEQ + l) * PSSM_NST + (obase - 256)];
        dst[0] = make_float4(acc[0], acc[1], acc[2], acc[3]);
        dst[1] = make_float4(acc[4], acc[5], acc[6], acc[7]);
    } else {
        float4* dst = (float4*)&g_C[(b * PSSM_SEQ + l) * PSSM_NST + (obase - 320)];
        dst[0] = make_float4(acc[0], acc[1], acc[2], acc[3]);
        dst[1] = make_float4(acc[4], acc[5], acc[6], acc[7]);
    }
}

// ============================================================
// Phase A (conv fused, single forward pass for BOTH dirs):
//   warp = d-pair; half-warp = one d; lane r holds states 4r..4r+3.
//   fwd summary: h = A*h + bx.    bwd summary: Bk += bx*P; P *= A.
// grid 512: blk = (b<<8)|(c<<3)|dg.  block 256 = 8 warps = 16 d.
// ============================================================
__global__ void __launch_bounds__(256) pssm_scanA_kernel(
    const float* __restrict__ cw, const float* __restrict__ cb)
{
    __shared__ float Bs[PSSM_CL * PSSM_NST];   // 16KB

    const int blk = blockIdx.x;
    const int dg  = blk & 7;              // 8 groups of 16 d
    const int c   = (blk >> 3) & 31;
    const int b   = blk >> 8;

    const int tid  = threadIdx.x;
    const int w    = tid >> 5;            // 0..7 d-pair
    const int lane = tid & 31;
    const int half = lane >> 4;
    const int r    = lane & 15;
    const int d    = dg * 16 + w * 2 + half;

    {   // stage B chunk: 1024 float4, 4/thread
        const float4* s4 = (const float4*)(g_B + (b * PSSM_SEQ + c * PSSM_CL) * PSSM_NST);
        float4* d4p = (float4*)Bs;
        #pragma unroll
        for (int i = 0; i < 4; i++)
            d4p[tid + 256 * i] = __ldg(&s4[tid + 256 * i]);
    }
    __syncthreads();

    const int off = (b * PSSM_DIN + d) * PSSM_SEQ + c * PSSM_CL;
    const float* dl  = g_delta + off;
    const float* xcl = g_xc + off;
    float* uw = g_u + off;
    float* vw = g_v + off;

    const float4 a4 = __ldg((const float4*)&g_a2[r * 4]);
    const float cw0 = __ldg(&cw[d * 4 + 0]);
    const float cw1 = __ldg(&cw[d * 4 + 1]);
    const float cw2 = __ldg(&cw[d * 4 + 2]);
    const float cw3 = __ldg(&cw[d * 4 + 3]);
    const float bias = __ldg(&cb[d]);

    float hf0 = 0.f, hf1 = 0.f, hf2 = 0.f, hf3 = 0.f;    // fwd end-state
    float bk0 = 0.f, bk1 = 0.f, bk2 = 0.f, bk3 = 0.f;    // bwd end-state
    float P0 = 1.f, P1 = 1.f, P2 = 1.f, P3 = 1.f;        // prefix product
    float ds = 0.f;

    #pragma unroll 2
    for (int s = 0; s < 16; s++) {
        const int lb = 4 * s;
        const float4 d4 = __ldg((const float4*)(dl + lb));
        const float4 xq = __ldg((const float4*)(xcl + lb));
        float4 xp;
        if (c == 0 && s == 0) xp = make_float4(0.f, 0.f, 0.f, 0.f);
        else                  xp = __ldg((const float4*)(xcl + lb - 4));

        // depthwise conv k=4 (cw0..cw3 hit x[l-3..l])
        float v0 = bias, v1 = bias, v2 = bias, v3 = bias;
        v0 = fmaf(cw0, xp.y, v0); v0 = fmaf(cw1, xp.z, v0);
        v0 = fmaf(cw2, xp.w, v0); v0 = fmaf(cw3, xq.x, v0);
        v1 = fmaf(cw0, xp.z, v1); v1 = fmaf(cw1, xp.w, v1);
        v1 = fmaf(cw2, xq.x, v1); v1 = fmaf(cw3, xq.y, v1);
        v2 = fmaf(cw0, xp.w, v2); v2 = fmaf(cw1, xq.x, v2);
        v2 = fmaf(cw2, xq.y, v2); v2 = fmaf(cw3, xq.z, v2);
        v3 = fmaf(cw0, xq.x, v3); v3 = fmaf(cw1, xq.y, v3);
        v3 = fmaf(cw2, xq.z, v3); v3 = fmaf(cw3, xq.w, v3);

        const float da[4] = {d4.x, d4.y, d4.z, d4.w};
        const float ua[4] = {da[0] * v0, da[1] * v1, da[2] * v2, da[3] * v3};

        if (r == 0) {      // one writer per d per 4-elem group
            *(float4*)(vw + lb) = make_float4(v0, v1, v2, v3);
            *(float4*)(uw + lb) = make_float4(ua[0], ua[1], ua[2], ua[3]);
        }

        #pragma unroll
        for (int k = 0; k < 4; k++) {
            const float e0 = exp2f(da[k] * a4.x);
            const float e1 = exp2f(da[k] * a4.y);
            const float e2 = exp2f(da[k] * a4.z);
            const float e3 = exp2f(da[k] * a4.w);
            const float4 B4 = *(const float4*)&Bs[(lb + k) * PSSM_NST + r * 4];
            const float t0 = ua[k] * B4.x;
            const float t1 = ua[k] * B4.y;
            const float t2 = ua[k] * B4.z;
            const float t3 = ua[k] * B4.w;
            bk0 = fmaf(t0, P0, bk0); bk1 = fmaf(t1, P1, bk1);   // uses P BEFORE update
            bk2 = fmaf(t2, P2, bk2); bk3 = fmaf(t3, P3, bk3);
            hf0 = fmaf(e0, hf0, t0); hf1 = fmaf(e1, hf1, t1);
            hf2 = fmaf(e2, hf2, t2); hf3 = fmaf(e3, hf3, t3);
            P0 *= e0; P1 *= e1; P2 *= e2; P3 *= e3;
            ds += da[k];
        }
    }

    const int hstep = PSSM_NC * PSSM_DIN * PSSM_NST;      // dir stride
    float* hl = g_hloc + (((b * 2) * PSSM_NC + c) * PSSM_DIN + d) * PSSM_NST;
    *(float4*)(hl + r * 4)         = make_float4(hf0, hf1, hf2, hf3);   // dir 0
    *(float4*)(hl + hstep + r * 4) = make_float4(bk0, bk1, bk2, bk3);   // dir 1
    if (r == 0)
        g_dS[(b * PSSM_NC + c) * PSSM_DIN + d] = ds;
}

// ============================================================
// Phase B: warp-parallel carry scan.  One warp per (b,dir,d,n);
// lane <-> chunk (reversed for bwd).  Hillis-Steele on
// (E1,h1)∘(E2,h2) = (E1E2, E2h1+h2).
// ============================================================
__global__ void __launch_bounds__(512) pssm_carry_kernel()
{
    const int wid  = (blockIdx.x * 512 + threadIdx.x) >> 5;  // 0..32767
    const int lane = threadIdx.x & 31;
    const int n    = wid & 63;
    const int d    = (wid >> 6) & 127;
    const int dir  = (wid >> 13) & 1;
    const int b    = wid >> 14;

    const int c = dir ? (31 - lane) : lane;
    const float a2n = g_a2[n];
    const int o = ((b * 2 + dir) * PSSM_NC + c) * PSSM_DIN * PSSM_NST
                + d * PSSM_NST + n;

    float h = g_hloc[o];
    float E = exp2f(a2n * g_dS[(b * PSSM_NC + c) * PSSM_DIN + d]);

    #pragma unroll
    for (int ofs = 1; ofs < 32; ofs <<= 1) {
        const float ph = __shfl_up_sync(0xffffffffu, h, ofs);
        const float pe = __shfl_up_sync(0xffffffffu, E, ofs);
        if (lane >= ofs) { h = fmaf(E, ph, h); E *= pe; }
    }
    const float ex = __shfl_up_sync(0xffffffffu, h, 1);
    g_carry[o] = (lane == 0) ? 0.f : ex;
}

// ============================================================
// Phase C body: warp = 4 d x 1 dir.  Lane: q = lane>>3 -> d,
// r8 = lane&7 -> 8 states (8*r8..8*r8+7).  All quads read the same
// B/C row -> smem broadcast serves 4 d per 256B.  Per-ts partial
// to warp tile (16 x 36: conflict-free STS, 16B-aligned conflict-
// free float4 readback); every 16 ts each lane reduces 2 cells.
// ============================================================
template<bool REV>
__device__ __forceinline__ void pssm_scanC_body(
    const float* __restrict__ dl, const float* __restrict__ ul,
    const float* __restrict__ Bsm, const float* __restrict__ Csm,
    float* __restrict__ tile, float* __restrict__ ysum,
    const float4 a40, const float4 a41,
    const float4 hc0, const float4 hc1,
    const int lane, const int r8, const int ycol_base)
{
    float h0 = hc0.x, h1 = hc0.y, h2 = hc0.z, h3 = hc0.w;
    float h4 = hc1.x, h5 = hc1.y, h6 = hc1.z, h7 = hc1.w;

    #pragma unroll
    for (int grp = 0; grp < 4; grp++) {
        #pragma unroll
        for (int si = 0; si < 4; si++) {
            const int s  = grp * 4 + si;
            const int lb = REV ? (60 - 4 * s) : (4 * s);
            const float4 d4 = __ldg((const float4*)(dl + lb));
            const float4 u4 = __ldg((const float4*)(ul + lb));
            const float da[4] = {d4.x, d4.y, d4.z, d4.w};
            const float ua[4] = {u4.x, u4.y, u4.z, u4.w};
            #pragma unroll
            for (int k = 0; k < 4; k++) {
                const int j = REV ? (3 - k) : k;      // compile-time
                const int l = lb + j;
                const float dj = da[j];
                const float uj = ua[j];
                const float e0 = exp2f(dj * a40.x);
                const float e1 = exp2f(dj * a40.y);
                const float e2 = exp2f(dj * a40.z);
                const float e3 = exp2f(dj * a40.w);
                const float e4 = exp2f(dj * a41.x);
                const float e5 = exp2f(dj * a41.y);
                const float e6 = exp2f(dj * a41.z);
                const float e7 = exp2f(dj * a41.w);
                const float4 B0 = *(const float4*)&Bsm[l * PSSM_NST + r8 * 8];
                const float4 B1 = *(const float4*)&Bsm[l * PSSM_NST + r8 * 8 + 4];
                const float4 C0 = *(const float4*)&Csm[l * PSSM_NST + r8 * 8];
                const float4 C1 = *(const float4*)&Csm[l * PSSM_NST + r8 * 8 + 4];
                h0 = fmaf(e0, h0, uj * B0.x);
                h1 = fmaf(e1, h1, uj * B0.y);
                h2 = fmaf(e2, h2, uj * B0.z);
                h3 = fmaf(e3, h3, uj * B0.w);
                h4 = fmaf(e4, h4, uj * B1.x);
                h5 = fmaf(e5, h5, uj * B1.y);
                h6 = fmaf(e6, h6, uj * B1.z);
                h7 = fmaf(e7, h7, uj * B1.w);
                float p = h0 * C0.x;
                p = fmaf(h1, C0.y, p);
                p = fmaf(h2, C0.z, p);
                p = fmaf(h3, C0.w, p);
                p = fmaf(h4, C1.x, p);
                p = fmaf(h5, C1.y, p);
                p = fmaf(h6, C1.z, p);
                p = fmaf(h7, C1.w, p);
                tile[(l & 15) * 36 + lane] = p;       // consecutive lanes, no conflict
            }
        }
        __syncwarp();
        // readback: 64 cells (16 rows x 4 q) -> 2 per lane
        const int lg = REV ? (48 - 16 * grp) : (16 * grp);
        #pragma unroll
        for (int i = 0; i < 2; i++) {
            const int cell = lane + 32 * i;
            const int rw = cell >> 2;                 // 0..15
            const int qq = cell & 3;
            const float4 v0 = *(const float4*)&tile[rw * 36 + qq * 8];
            const float4 v1 = *(const float4*)&tile[rw * 36 + qq * 8 + 4];
            const float sum = ((v0.x + v0.y) + (v0.z + v0.w))
                            + ((v1.x + v1.y) + (v1.z + v1.w));
            ysum[(lg + rw) * 33 + (ycol_base + qq * 2)] = sum;
        }
        __syncwarp();   // protect tile before next group's writes
    }
}

// grid 512: blk = (b<<8)|(c<<3)|dg.  block 256 = 8 warps:
//   warp w: dir = w&1 (uniform), quad-group qg = w>>1 (4 d each).
__global__ void __launch_bounds__(256) pssm_scanC_kernel(float* __restrict__ y,
                                                         const float* __restrict__ Dp)
{
    extern __shared__ float smC[];
    float* Bsm  = smC + SMC_B;
    float* Csm  = smC + SMC_C;
    float* tile = smC + SMC_TILE;
    float* ysum = smC + SMC_YSUM;
    float* vs   = smC + SMC_VS;

    const int blk = blockIdx.x;
    const int dg  = blk & 7;              // 8 groups of 16 d
    const int c   = (blk >> 3) & 31;
    const int b   = blk >> 8;

    const int tid  = threadIdx.x;
    const int w    = tid >> 5;            // 0..7
    const int lane = tid & 31;
    const int dir  = w & 1;               // warp-uniform
    const int qg   = w >> 1;              // 0..3
    const int q    = lane >> 3;           // 0..3 -> d within quad-group
    const int r8   = lane & 7;            // 8 states
    const int dloc = qg * 4 + q;          // 0..15
    const int d    = dg * 16 + dloc;

    {   // stage B and C: 1024 float4 each, 4+4 per thread
        const int gbase = (b * PSSM_SEQ + c * PSSM_CL) * PSSM_NST;
        const float4* sB = (const float4*)(g_B + gbase);
        const float4* sC = (const float4*)(g_C + gbase);
        float4* dB = (float4*)Bsm;
        float4* dC = (float4*)Csm;
        #pragma unroll
        for (int i = 0; i < 4; i++) {
            dB[tid + 256 * i] = __ldg(&sB[tid + 256 * i]);
            dC[tid + 256 * i] = __ldg(&sC[tid + 256 * i]);
        }
    }
    {   // stage x_conv tile: 16 d x 64 l, 256 float4 loads, scalar scatter
        const int dd = tid >> 4;
        const int c4 = (tid & 15) * 4;
        const float4 v4 = __ldg((const float4*)
            (g_v + (b * PSSM_DIN + dg * 16 + dd) * PSSM_SEQ + c * PSSM_CL + c4));
        vs[dd * 65 + c4 + 0] = v4.x;
        vs[dd * 65 + c4 + 1] = v4.y;
        vs[dd * 65 + c4 + 2] = v4.z;
        vs[dd * 65 + c4 + 3] = v4.w;
    }
    __syncthreads();

    const int off = (b * PSSM_DIN + d) * PSSM_SEQ + c * PSSM_CL;
    const float* dl = g_delta + off;
    const float* ul = g_u + off;
    const float4 a40 = __ldg((const float4*)&g_a2[r8 * 8]);
    const float4 a41 = __ldg((const float4*)&g_a2[r8 * 8 + 4]);

    const float* cr = g_carry +
        ((((b * 2 + dir) * PSSM_NC + c) * PSSM_DIN + d) * PSSM_NST);
    const float4 hc0 = *(const float4*)(cr + r8 * 8);
    const float4 hc1 = *(const float4*)(cr + r8 * 8 + 4);

    float* wtile = tile + w * 576;                 // 16 x 36 floats
    const int ycol_base = qg * 8 + dir;            // body adds qq*2

    if (dir == 0)
        pssm_scanC_body<false>(dl, ul, Bsm, Csm, wtile, ysum,
                               a40, a41, hc0, hc1, lane, r8, ycol_base);
    else
        pssm_scanC_body<true >(dl, ul, Bsm, Csm, wtile, ysum,
                               a40, a41, hc0, hc1, lane, r8, ycol_base);
    __syncthreads();

    // output: 1024 cells = 64 l x 16 d, 4 per thread, coalesced stores
    #pragma unroll
    for (int i = 0; i < 4; i++) {
        const int cell = tid + 256 * i;
        const int l  = cell >> 4;
        const int dd = cell & 15;
        const int dglob = dg * 16 + dd;
        const float val = ysum[l * 33 + dd * 2] + ysum[l * 33 + dd * 2 + 1]
                        + __ldg(&Dp[dglob]) * vs[dd * 65 + l];
        y[(size_t)(b * PSSM_SEQ + c * PSSM_CL + l) * PSSM_DIN + dglob] = val;
    }
}

// ============================================================
extern "C" void kernel_launch(void* const* d_in, const int* in_sizes, int n_in,
                              void* d_out, int out_size)
{
    const float* x  = (const float*)d_in[0];
    const float* W  = (const float*)d_in[1];
    const float* cw = (const float*)d_in[2];
    const float* cb = (const float*)d_in[3];
    const float* A  = (const float*)d_in[4];
    const float* Dp = (const float*)d_in[5];
    float* y = (float*)d_out;

    // opt-in to >48KB dynamic smem (idempotent; no allocation)
    static int smem_attr_set = 0;
    if (!smem_attr_set) {
        cudaFuncSetAttribute(pssm_scanC_kernel,
                             cudaFuncAttributeMaxDynamicSharedMemorySize,
                             SMC_TOTAL_BYTES);
        smem_attr_set = 1;
    }

    dim3 pg(64, 12);
    pssm_proj_kernel<<<pg, 256>>>(x, W, A);
    pssm_scanA_kernel<<<512, 256>>>(cw, cb);
    pssm_carry_kernel<<<2048, 512>>>();
    pssm_scanC_kernel<<<512, 256, SMC_TOTAL_BYTES>>>(y, Dp);
}

// round 13
// speedup vs baseline: 1.2516x; 1.2516x over previous
#include <cuda_runtime.h>

#define PSSM_BATCH  2
#define PSSM_SEQ    2048
#define PSSM_DIN    128
#define PSSM_NST    64
#define PSSM_NC     32      // chunks per sequence
#define PSSM_CL     64      // chunk length
#define PSSM_LOG2E  1.4426950408889634f

// ---- scratch (static device arrays; no allocation) ----
__device__ float g_xc   [PSSM_BATCH*PSSM_DIN*PSSM_SEQ];            // (b,d,l)
__device__ float g_delta[PSSM_BATCH*PSSM_DIN*PSSM_SEQ];            // (b,d,l) sigmoid applied
__device__ float g_u    [PSSM_BATCH*PSSM_DIN*PSSM_SEQ];            // (b,d,l) delta*x_conv
__device__ float g_v    [PSSM_BATCH*PSSM_DIN*PSSM_SEQ];            // (b,d,l) x_conv
__device__ float g_B    [PSSM_BATCH*PSSM_SEQ*PSSM_NST];            // (b,l,n)
__device__ float g_C    [PSSM_BATCH*PSSM_SEQ*PSSM_NST];            // (b,l,n)
__device__ float g_a2   [PSSM_NST];                                // rowsum(A)*log2(e)
__device__ float g_hloc [PSSM_BATCH*2*PSSM_NC*PSSM_DIN*PSSM_NST];  // (b,dir,c,d,n)
__device__ float g_carry[PSSM_BATCH*2*PSSM_NC*PSSM_DIN*PSSM_NST];  // (b,dir,c,d,n)
__device__ float g_dS   [PSSM_BATCH*PSSM_NC*PSSM_DIN];             // (b,c,d)

// scanC dynamic smem layout (floats)  -- R9-proven layout
#define SMC_B     0                       // 4096
#define SMC_C     4096                    // 4096
#define SMC_TILE  8192                    // 16 warps x (16 x 36) = 9216
#define SMC_YSUM  17408                   // 64 x 33 = 2112
#define SMC_VS    19520                   // 16 x 65 = 1040
#define SMC_TOTAL_BYTES (20560 * 4)       // 82240 B

// ============================================================
// Stage 1: projection xp = x @ W^T.
// grid (64, 12), block 256.  bx -> 64-token tile, by -> 32 outputs.
// ============================================================
__global__ void __launch_bounds__(256) pssm_proj_kernel(
    const float* __restrict__ x,
    const float* __restrict__ W,
    const float* __restrict__ A)
{
    __shared__ float xsT[64 * 65];    // [k][t], pad 65  (16.6KB)
    __shared__ float Wsm[32 * 64];    // [i][k]          (8KB)

    const int tid = threadIdx.x;
    const int og  = blockIdx.y;                  // 0..11
    const int t0  = blockIdx.x * 64;             // global token base

    if (blockIdx.x == 0 && blockIdx.y == 0 && tid < PSSM_NST) {
        float s = 0.f;
        const float* ar = A + tid * PSSM_NST;
        #pragma unroll 8
        for (int j = 0; j < PSSM_NST; j++) s += ar[j];
        g_a2[tid] = s * PSSM_LOG2E;
    }

    {
        const float4* wsrc = (const float4*)(W + og * 32 * 64);
        float4* wdst = (float4*)Wsm;
        wdst[tid]       = __ldg(&wsrc[tid]);
        wdst[tid + 256] = __ldg(&wsrc[tid + 256]);
    }

    #pragma unroll
    for (int i = 0; i < 4; i++) {
        const int f  = tid + 256 * i;
        const int t  = f >> 4;
        const int c4 = (f & 15) * 4;
        const float4 v = __ldg((const float4*)(x + (t0 + t) * 64 + c4));
        xsT[(c4 + 0) * 65 + t] = v.x;
        xsT[(c4 + 1) * 65 + t] = v.y;
        xsT[(c4 + 2) * 65 + t] = v.z;
        xsT[(c4 + 3) * 65 + t] = v.w;
    }
    __syncthreads();

    const int oc = tid >> 6;          // 0..3
    const int t  = tid & 63;
    const int token = t0 + t;
    const int b = token >> 11;
    const int l = token & 2047;

    float acc[8] = {0.f, 0.f, 0.f, 0.f, 0.f, 0.f, 0.f, 0.f};

    #pragma unroll 4
    for (int k4 = 0; k4 < 16; k4++) {
        const int k = k4 * 4;
        const float x0 = xsT[(k + 0) * 65 + t];
        const float x1 = xsT[(k + 1) * 65 + t];
        const float x2 = xsT[(k + 2) * 65 + t];
        const float x3 = xsT[(k + 3) * 65 + t];
        #pragma unroll
        for (int i = 0; i < 8; i++) {
            const float4 w4 = *(const float4*)&Wsm[(oc * 8 + i) * 64 + k];
            acc[i] = fmaf(w4.x, x0, acc[i]);
            acc[i] = fmaf(w4.y, x1, acc[i]);
            acc[i] = fmaf(w4.z, x2, acc[i]);
            acc[i] = fmaf(w4.w, x3, acc[i]);
        }
    }

    const int obase = og * 32 + oc * 8;          // block-uniform segment
    if (obase < 128) {
        #pragma unroll
        for (int i = 0; i < 8; i++)
            g_xc[(b * PSSM_DIN + obase + i) * PSSM_SEQ + l] = acc[i];
    } else if (obase < 256) {
        #pragma unroll
        for (int i = 0; i < 8; i++)
            g_delta[(b * PSSM_DIN + (obase - 128 + i)) * PSSM_SEQ + l] =
                __fdividef(1.f, 1.f + __expf(-acc[i]));
    } else if (obase < 320) {
        float4* dst = (float4*)&g_B[(b * PSSM_SEQ + l) * PSSM_NST + (obase - 256)];
        dst[0] = make_float4(acc[0], acc[1], acc[2], acc[3]);
        dst[1] = make_float4(acc[4], acc[5], acc[6], acc[7]);
    } else {
        float4* dst = (float4*)&g_C[(b * PSSM_SEQ + l) * PSSM_NST + (obase - 320)];
        dst[0] = make_float4(acc[0], acc[1], acc[2], acc[3]);
        dst[1] = make_float4(acc[4], acc[5], acc[6], acc[7]);
    }
}

// ============================================================
// Phase A (conv fused, single forward pass for BOTH dirs):
//   warp = d-pair; half-warp = one d; lane r holds states 4r..4r+3.
//   fwd summary: h = A*h + bx.    bwd summary: Bk += bx*P; P *= A.
//   Prefetched d4/xq; xp reuses previous group's xq (forward order).
// grid 512: blk = (b<<8)|(c<<3)|dg.  block 256 = 8 warps = 16 d.
// ============================================================
__global__ void __launch_bounds__(256) pssm_scanA_kernel(
    const float* __restrict__ cw, const float* __restrict__ cb)
{
    __shared__ float Bs[PSSM_CL * PSSM_NST];   // 16KB

    const int blk = blockIdx.x;
    const int dg  = blk & 7;              // 8 groups of 16 d
    const int c   = (blk >> 3) & 31;
    const int b   = blk >> 8;

    const int tid  = threadIdx.x;
    const int w    = tid >> 5;            // 0..7 d-pair
    const int lane = tid & 31;
    const int half = lane >> 4;
    const int r    = lane & 15;
    const int d    = dg * 16 + w * 2 + half;

    {   // stage B chunk: 1024 float4, 4/thread
        const float4* s4 = (const float4*)(g_B + (b * PSSM_SEQ + c * PSSM_CL) * PSSM_NST);
        float4* d4p = (float4*)Bs;
        #pragma unroll
        for (int i = 0; i < 4; i++)
            d4p[tid + 256 * i] = __ldg(&s4[tid + 256 * i]);
    }
    __syncthreads();

    const int off = (b * PSSM_DIN + d) * PSSM_SEQ + c * PSSM_CL;
    const float* dl  = g_delta + off;
    const float* xcl = g_xc + off;
    float* uw = g_u + off;
    float* vw = g_v + off;

    const float4 a4 = __ldg((const float4*)&g_a2[r * 4]);
    const float cw0 = __ldg(&cw[d * 4 + 0]);
    const float cw1 = __ldg(&cw[d * 4 + 1]);
    const float cw2 = __ldg(&cw[d * 4 + 2]);
    const float cw3 = __ldg(&cw[d * 4 + 3]);
    const float bias = __ldg(&cb[d]);

    float hf0 = 0.f, hf1 = 0.f, hf2 = 0.f, hf3 = 0.f;    // fwd end-state
    float bk0 = 0.f, bk1 = 0.f, bk2 = 0.f, bk3 = 0.f;    // bwd end-state
    float P0 = 1.f, P1 = 1.f, P2 = 1.f, P3 = 1.f;        // prefix product
    float ds = 0.f;

    // prefetch pipeline: xp(s) == xq(s-1)
    float4 xp = (c == 0) ? make_float4(0.f, 0.f, 0.f, 0.f)
                         : __ldg((const float4*)(xcl - 4));
    float4 xq = __ldg((const float4*)(xcl));
    float4 d4 = __ldg((const float4*)(dl));

    #pragma unroll 4
    for (int s = 0; s < 16; s++) {
        const int lb = 4 * s;
        float4 xqn, d4n;
        if (s < 15) {
            xqn = __ldg((const float4*)(xcl + lb + 4));
            d4n = __ldg((const float4*)(dl + lb + 4));
        }

        // depthwise conv k=4 (cw0..cw3 hit x[l-3..l])
        float v0 = bias, v1 = bias, v2 = bias, v3 = bias;
        v0 = fmaf(cw0, xp.y, v0); v0 = fmaf(cw1, xp.z, v0);
        v0 = fmaf(cw2, xp.w, v0); v0 = fmaf(cw3, xq.x, v0);
        v1 = fmaf(cw0, xp.z, v1); v1 = fmaf(cw1, xp.w, v1);
        v1 = fmaf(cw2, xq.x, v1); v1 = fmaf(cw3, xq.y, v1);
        v2 = fmaf(cw0, xp.w, v2); v2 = fmaf(cw1, xq.x, v2);
        v2 = fmaf(cw2, xq.y, v2); v2 = fmaf(cw3, xq.z, v2);
        v3 = fmaf(cw0, xq.x, v3); v3 = fmaf(cw1, xq.y, v3);
        v3 = fmaf(cw2, xq.z, v3); v3 = fmaf(cw3, xq.w, v3);

        const float da[4] = {d4.x, d4.y, d4.z, d4.w};
        const float ua[4] = {da[0] * v0, da[1] * v1, da[2] * v2, da[3] * v3};

        if (r == 0) {      // one writer per d per 4-elem group
            *(float4*)(vw + lb) = make_float4(v0, v1, v2, v3);
            *(float4*)(uw + lb) = make_float4(ua[0], ua[1], ua[2], ua[3]);
        }

        #pragma unroll
        for (int k = 0; k < 4; k++) {
            const float e0 = exp2f(da[k] * a4.x);
            const float e1 = exp2f(da[k] * a4.y);
            const float e2 = exp2f(da[k] * a4.z);
            const float e3 = exp2f(da[k] * a4.w);
            const float4 B4 = *(const float4*)&Bs[(lb + k) * PSSM_NST + r * 4];
            const float t0 = ua[k] * B4.x;
            const float t1 = ua[k] * B4.y;
            const float t2 = ua[k] * B4.z;
            const float t3 = ua[k] * B4.w;
            bk0 = fmaf(t0, P0, bk0); bk1 = fmaf(t1, P1, bk1);   // uses P BEFORE update
            bk2 = fmaf(t2, P2, bk2); bk3 = fmaf(t3, P3, bk3);
            hf0 = fmaf(e0, hf0, t0); hf1 = fmaf(e1, hf1, t1);
            hf2 = fmaf(e2, hf2, t2); hf3 = fmaf(e3, hf3, t3);
            P0 *= e0; P1 *= e1; P2 *= e2; P3 *= e3;
            ds += da[k];
        }

        xp = xq;
        if (s < 15) { xq = xqn; d4 = d4n; }
    }

    const int hstep = PSSM_NC * PSSM_DIN * PSSM_NST;      // dir stride
    float* hl = g_hloc + (((b * 2) * PSSM_NC + c) * PSSM_DIN + d) * PSSM_NST;
    *(float4*)(hl + r * 4)         = make_float4(hf0, hf1, hf2, hf3);   // dir 0
    *(float4*)(hl + hstep + r * 4) = make_float4(bk0, bk1, bk2, bk3);   // dir 1
    if (r == 0)
        g_dS[(b * PSSM_NC + c) * PSSM_DIN + d] = ds;
}

// ============================================================
// Phase B: warp-parallel carry scan.  One warp per (b,dir,d,n);
// lane <-> chunk (reversed for bwd).  Hillis-Steele on
// (E1,h1)∘(E2,h2) = (E1E2, E2h1+h2).
// ============================================================
__global__ void __launch_bounds__(512) pssm_carry_kernel()
{
    const int wid  = (blockIdx.x * 512 + threadIdx.x) >> 5;  // 0..32767
    const int lane = threadIdx.x & 31;
    const int n    = wid & 63;
    const int d    = (wid >> 6) & 127;
    const int dir  = (wid >> 13) & 1;
    const int b    = wid >> 14;

    const int c = dir ? (31 - lane) : lane;
    const float a2n = g_a2[n];
    const int o = ((b * 2 + dir) * PSSM_NC + c) * PSSM_DIN * PSSM_NST
                + d * PSSM_NST + n;

    float h = g_hloc[o];
    float E = exp2f(a2n * g_dS[(b * PSSM_NC + c) * PSSM_DIN + d]);

    #pragma unroll
    for (int ofs = 1; ofs < 32; ofs <<= 1) {
        const float ph = __shfl_up_sync(0xffffffffu, h, ofs);
        const float pe = __shfl_up_sync(0xffffffffu, E, ofs);
        if (lane >= ofs) { h = fmaf(E, ph, h); E *= pe; }
    }
    const float ex = __shfl_up_sync(0xffffffffu, h, 1);
    g_carry[o] = (lane == 0) ? 0.f : ex;
}

// ============================================================
// Phase C body (R9-proven layout + d/u prefetch):
// warp = (d-pair, dir); half-warp = one d; lane r holds states
// 4r..4r+3.  Per-ts partial to warp tile (16 x 36, conflict-free
// STS & aligned float4 readback); flush every 16 ts.  No shuffles.
// ============================================================
template<bool REV>
__device__ __forceinline__ void pssm_scanC_body(
    const float* __restrict__ dl, const float* __restrict__ ul,
    const float* __restrict__ Bsm, const float* __restrict__ Csm,
    float* __restrict__ tile, float* __restrict__ ysum,
    const float4 a4, const float4 hc,
    const int half, const int r, const int ycol)
{
    float h0 = hc.x, h1 = hc.y, h2 = hc.z, h3 = hc.w;
    const int wcol = half * 16 + r;

    float4 d4 = __ldg((const float4*)(dl + (REV ? 60 : 0)));
    float4 u4 = __ldg((const float4*)(ul + (REV ? 60 : 0)));

    #pragma unroll
    for (int grp = 0; grp < 4; grp++) {
        #pragma unroll
        for (int si = 0; si < 4; si++) {
            const int s  = grp * 4 + si;
            const int lb = REV ? (60 - 4 * s) : (4 * s);
            float4 d4n, u4n;
            if (s < 15) {
                const int lbn = REV ? (56 - 4 * s) : (4 * s + 4);
                d4n = __ldg((const float4*)(dl + lbn));
                u4n = __ldg((const float4*)(ul + lbn));
            }
            const float da[4] = {d4.x, d4.y, d4.z, d4.w};
            const float ua[4] = {u4.x, u4.y, u4.z, u4.w};
            #pragma unroll
            for (int k = 0; k < 4; k++) {
                const int j = REV ? (3 - k) : k;      // compile-time
                const int l = lb + j;
                const float e0 = exp2f(da[j] * a4.x);
                const float e1 = exp2f(da[j] * a4.y);
                const float e2 = exp2f(da[j] * a4.z);
                const float e3 = exp2f(da[j] * a4.w);
                const float4 B4 = *(const float4*)&Bsm[l * PSSM_NST + r * 4];
                const float4 C4 = *(const float4*)&Csm[l * PSSM_NST + r * 4];
                h0 = fmaf(e0, h0, ua[j] * B4.x);
                h1 = fmaf(e1, h1, ua[j] * B4.y);
                h2 = fmaf(e2, h2, ua[j] * B4.z);
                h3 = fmaf(e3, h3, ua[j] * B4.w);
                float p = h0 * C4.x;
                p = fmaf(h1, C4.y, p);
                p = fmaf(h2, C4.z, p);
                p = fmaf(h3, C4.w, p);
                tile[(l & 15) * 36 + wcol] = p;       // consecutive lanes, no conflict
            }
            if (s < 15) { d4 = d4n; u4 = u4n; }
        }
        __syncwarp();
        // readback: lane (half,r) sums row r over its half's 16 cols
        const float4 v0 = *(const float4*)&tile[r * 36 + half * 16 + 0];
        const float4 v1 = *(const float4*)&tile[r * 36 + half * 16 + 4];
        const float4 v2 = *(const float4*)&tile[r * 36 + half * 16 + 8];
        const float4 v3 = *(const float4*)&tile[r * 36 + half * 16 + 12];
        const float sum =
            (((v0.x + v0.y) + (v0.z + v0.w)) + ((v1.x + v1.y) + (v1.z + v1.w)))
          + (((v2.x + v2.y) + (v2.z + v2.w)) + ((v3.x + v3.y) + (v3.z + v3.w)));
        const int lg = REV ? (48 - 16 * grp) : (16 * grp);
        ysum[(lg + r) * 33 + ycol] = sum;
        __syncwarp();   // protect tile before next group's writes
    }
}

// grid 512: blk = (b<<8)|(c<<3)|dg.  block 512 = 16 warps:
//   warp w: dir = w&1 (uniform), d-pair = w>>1; half-warp = one d.
__global__ void __launch_bounds__(512) pssm_scanC_kernel(float* __restrict__ y,
                                                         const float* __restrict__ Dp)
{
    extern __shared__ float smC[];
    float* Bsm  = smC + SMC_B;
    float* Csm  = smC + SMC_C;
    float* tile = smC + SMC_TILE;
    float* ysum = smC + SMC_YSUM;
    float* vs   = smC + SMC_VS;

    const int blk = blockIdx.x;
    const int dg  = blk & 7;
    const int c   = (blk >> 3) & 31;
    const int b   = blk >> 8;

    const int tid  = threadIdx.x;
    const int w    = tid >> 5;
    const int lane = tid & 31;
    const int dir  = w & 1;               // warp-uniform
    const int pr   = w >> 1;              // d-pair 0..7
    const int half = lane >> 4;
    const int r    = lane & 15;
    const int dloc = pr * 2 + half;
    const int d    = dg * 16 + dloc;

    {   // stage B and C: 1024 float4 each, 2+2 per thread
        const int gbase = (b * PSSM_SEQ + c * PSSM_CL) * PSSM_NST;
        const float4* sB = (const float4*)(g_B + gbase);
        const float4* sC = (const float4*)(g_C + gbase);
        float4* dB = (float4*)Bsm;
        float4* dC = (float4*)Csm;
        #pragma unroll
        for (int i = 0; i < 2; i++) {
            dB[tid + 512 * i] = __ldg(&sB[tid + 512 * i]);
            dC[tid + 512 * i] = __ldg(&sC[tid + 512 * i]);
        }
    }
    #pragma unroll
    for (int i = 0; i < 2; i++) {
        const int e  = tid + 512 * i;
        const int dd = e >> 6, lv = e & 63;
        vs[dd * 65 + lv] =
            g_v[(b * PSSM_DIN + dg * 16 + dd) * PSSM_SEQ + c * PSSM_CL + lv];
    }
    __syncthreads();

    const int off = (b * PSSM_DIN + d) * PSSM_SEQ + c * PSSM_CL;
    const float* dl = g_delta + off;
    const float* ul = g_u + off;
    const float4 a4 = __ldg((const float4*)&g_a2[r * 4]);

    const float* cr = g_carry +
        ((((b * 2 + dir) * PSSM_NC + c) * PSSM_DIN + d) * PSSM_NST);
    const float4 hc = *(const float4*)(cr + r * 4);

    float* wtile = tile + w * 576;                 // 16 x 36 floats
    const int ycol = dloc * 2 + dir;

    if (dir == 0)
        pssm_scanC_body<false>(dl, ul, Bsm, Csm, wtile, ysum, a4, hc, half, r, ycol);
    else
        pssm_scanC_body<true >(dl, ul, Bsm, Csm, wtile, ysum, a4, hc, half, r, ycol);
    __syncthreads();

    // output: 1024 cells = 64 l x 16 d, 2 per thread, coalesced stores
    #pragma unroll
    for (int i = 0; i < 2; i++) {
        const int cell = tid + 512 * i;
        const int l  = cell >> 4;
        const int dd = cell & 15;
        const int dglob = dg * 16 + dd;
        const float val = ysum[l * 33 + dd * 2] + ysum[l * 33 + dd * 2 + 1]
                        + __ldg(&Dp[dglob]) * vs[dd * 65 + l];
        y[(size_t)(b * PSSM_SEQ + c * PSSM_CL + l) * PSSM_DIN + dglob] = val;
    }
}

// ============================================================
extern "C" void kernel_launch(void* const* d_in, const int* in_sizes, int n_in,
                              void* d_out, int out_size)
{
    const float* x  = (const float*)d_in[0];
    const float* W  = (const float*)d_in[1];
    const float* cw = (const float*)d_in[2];
    const float* cb = (const float*)d_in[3];
    const float* A  = (const float*)d_in[4];
    const float* Dp = (const float*)d_in[5];
    float* y = (float*)d_out;

    // opt-in to >48KB dynamic smem (idempotent; no allocation)
    static int smem_attr_set = 0;
    if (!smem_attr_set) {
        cudaFuncSetAttribute(pssm_scanC_kernel,
                             cudaFuncAttributeMaxDynamicSharedMemorySize,
                             SMC_TOTAL_BYTES);
        smem_attr_set = 1;
    }

    dim3 pg(64, 12);
    pssm_proj_kernel<<<pg, 256>>>(x, W, A);
    pssm_scanA_kernel<<<512, 256>>>(cw, cb);
    pssm_carry_kernel<<<2048, 512>>>();
    pssm_scanC_kernel<<<512, 512, SMC_TOTAL_BYTES>>>(y, Dp);
}